// round 13
// baseline (speedup 1.0000x reference)
#include <cuda_runtime.h>
#include <cuda_fp16.h>
#include <cstdint>

// ---------------------------------------------------------------------------
// Problem constants
// ---------------------------------------------------------------------------
constexpr int BB   = 8;
constexpr int NP   = 8192;
constexpr int SP   = 2048;
constexpr int CIN  = 256;
constexpr int CSK  = 128;
constexpr int C0   = 384;     // IN+SKIP
constexpr int C1   = 256;     // OUT
constexpr int CE   = 1024;    // OUT*EXP
constexpr int MTOT = BB * NP; // 65536 rows

// ---------------------------------------------------------------------------
// Scratch (device globals; no dynamic allocation allowed)
// ---------------------------------------------------------------------------
static __device__ __half g_A0[MTOT * C0];   // stage0 A plane (fp16)
static __device__ __half g_X1[MTOT * C1];   // stage1 A plane
static __device__ __half g_X2[MTOT * CE];   // stage2 A plane
static __device__ __half g_W0[C1 * C0];
static __device__ __half g_W1[CE * C1];
static __device__ __half g_W2[C1 * CE];
static __device__ float g_p2t[BB * SP * CIN];  // points2 transposed [b, s, c]
static __device__ float g_y1 [MTOT * C1];      // conv0 out (pre-GN)
static __device__ float g_h1 [MTOT * CE];      // conv1 out (pre-GN)
static __device__ float g_h2 [MTOT * C1];      // conv2 out (pre-GN)
static __device__ float g_sum[3 * 64];
static __device__ float g_sqs[3 * 64];
static __device__ float g_cA0[BB * C1], g_cB0[BB * C1];
static __device__ float g_cA1[BB * CE], g_cB1[BB * CE];
static __device__ float g_cA2[BB * C1], g_cB2[BB * C1];
static __device__ float g_scale[BB * C1], g_shift[BB * C1];

__device__ __forceinline__ float silu_f(float x) {
    return __fdividef(x, 1.0f + __expf(-x));
}

// ---------------------------------------------------------------------------
// MMA / cp.async helpers (legacy fp16 tensor-core path; plain sm_100 target)
// ---------------------------------------------------------------------------
__device__ __forceinline__ uint32_t sptr(const void* p) {
    return (uint32_t)__cvta_generic_to_shared(p);
}
__device__ __forceinline__ void ldmx4(uint32_t* r, uint32_t addr) {
    asm volatile("ldmatrix.sync.aligned.m8n8.x4.shared.b16 {%0,%1,%2,%3}, [%4];\n"
                 : "=r"(r[0]), "=r"(r[1]), "=r"(r[2]), "=r"(r[3]) : "r"(addr));
}
__device__ __forceinline__ void mma16816(float* c, const uint32_t* a, const uint32_t* b) {
    asm volatile(
        "mma.sync.aligned.m16n8k16.row.col.f32.f16.f16.f32 "
        "{%0,%1,%2,%3}, {%4,%5,%6,%7}, {%8,%9}, {%0,%1,%2,%3};\n"
        : "+f"(c[0]), "+f"(c[1]), "+f"(c[2]), "+f"(c[3])
        : "r"(a[0]), "r"(a[1]), "r"(a[2]), "r"(a[3]), "r"(b[0]), "r"(b[1]));
}
__device__ __forceinline__ void cp16(uint32_t dst, const void* src) {
    asm volatile("cp.async.cg.shared.global [%0], [%1], 16;\n" :: "r"(dst), "l"(src));
}
__device__ __forceinline__ void cp_commit() {
    asm volatile("cp.async.commit_group;\n" ::: "memory");
}
template <int N>
__device__ __forceinline__ void cp_wait() {
    asm volatile("cp.async.wait_group %0;\n" :: "n"(N) : "memory");
}

// ---------------------------------------------------------------------------
// Zero the stats accumulators
// ---------------------------------------------------------------------------
__global__ void zero_k() {
    int i = threadIdx.x;
    if (i < 192) { g_sum[i] = 0.0f; g_sqs[i] = 0.0f; }
}

// ---------------------------------------------------------------------------
// Weight convert: fp32 -> fp16 plane (8 elems/thread)
// ---------------------------------------------------------------------------
template <int WS>
__global__ void wsplit_k(const float* __restrict__ w, int n8) {
    int i = blockIdx.x * 256 + threadIdx.x;
    if (i >= n8) return;
    __half* hi = (WS == 0) ? g_W0 : (WS == 1 ? g_W1 : g_W2);
    const float4* wp = (const float4*)w + 2 * i;
    float4 a = wp[0], b = wp[1];
    __half h[8];
    h[0] = __float2half(a.x); h[1] = __float2half(a.y);
    h[2] = __float2half(a.z); h[3] = __float2half(a.w);
    h[4] = __float2half(b.x); h[5] = __float2half(b.y);
    h[6] = __float2half(b.z); h[7] = __float2half(b.w);
    *(uint4*)(hi + (size_t)i * 8) = *(uint4*)h;
}

// ---------------------------------------------------------------------------
// Activation convert: x -> silu(x*cA + cB) -> fp16 plane (8 elems/thread)
// ---------------------------------------------------------------------------
template <int STAGE>
__global__ void asplit_k() {
    constexpr int C = (STAGE == 1) ? C1 : CE;
    const float* X  = (STAGE == 1) ? g_y1  : g_h1;
    const float* cA = (STAGE == 1) ? g_cA0 : g_cA1;
    const float* cB = (STAGE == 1) ? g_cB0 : g_cB1;
    __half* oh = (STAGE == 1) ? g_X1 : g_X2;

    size_t i = (size_t)blockIdx.x * 256 + threadIdx.x;   // per 8 elements
    int m  = (int)(i / (C / 8));
    int c0 = (int)(i % (C / 8)) * 8;
    int b  = m >> 13;
    const float4* xp = (const float4*)(X + (size_t)m * C + c0);
    float4 x0 = xp[0], x1 = xp[1];
    const float* a = cA + b * C + c0;
    const float* s = cB + b * C + c0;
    __half h[8];
    h[0] = __float2half(silu_f(x0.x * a[0] + s[0]));
    h[1] = __float2half(silu_f(x0.y * a[1] + s[1]));
    h[2] = __float2half(silu_f(x0.z * a[2] + s[2]));
    h[3] = __float2half(silu_f(x0.w * a[3] + s[3]));
    h[4] = __float2half(silu_f(x1.x * a[4] + s[4]));
    h[5] = __float2half(silu_f(x1.y * a[5] + s[5]));
    h[6] = __float2half(silu_f(x1.z * a[6] + s[6]));
    h[7] = __float2half(silu_f(x1.w * a[7] + s[7]));
    *(uint4*)(oh + (size_t)m * C + c0) = *(uint4*)h;
}

// ---------------------------------------------------------------------------
// Transpose points1 [B,128,N] -> stage0 A plane, columns [0,128)
// ---------------------------------------------------------------------------
__global__ void tr_p1_k(const float* __restrict__ src) {
    __shared__ float t[32][33];
    int b  = blockIdx.z;
    int n0 = blockIdx.x * 32;
    int c0 = blockIdx.y * 32;
    int tx = threadIdx.x, ty = threadIdx.y;
#pragma unroll
    for (int i = 0; i < 4; i++) {
        int cl = ty + i * 8;
        t[cl][tx] = src[((size_t)b * CSK + (c0 + cl)) * NP + n0 + tx];
    }
    __syncthreads();
#pragma unroll
    for (int i = 0; i < 4; i++) {
        int nl = ty + i * 8;
        size_t m = (size_t)b * NP + n0 + nl;
        g_A0[m * C0 + c0 + tx] = __float2half(t[tx][nl]);
    }
}

// ---------------------------------------------------------------------------
// Transpose points2 [B,256,S] -> g_p2t [b, s, c]
// ---------------------------------------------------------------------------
__global__ void tr_p2_k(const float* __restrict__ src) {
    __shared__ float t[32][33];
    int b  = blockIdx.z;
    int s0 = blockIdx.x * 32;
    int c0 = blockIdx.y * 32;
    int tx = threadIdx.x, ty = threadIdx.y;
#pragma unroll
    for (int i = 0; i < 4; i++) {
        int cl = ty + i * 8;
        t[cl][tx] = src[((size_t)b * CIN + (c0 + cl)) * SP + s0 + tx];
    }
    __syncthreads();
#pragma unroll
    for (int i = 0; i < 4; i++) {
        int sl = ty + i * 8;
        g_p2t[((size_t)b * SP + (s0 + sl)) * CIN + c0 + tx] = t[tx][sl];
    }
}

// ---------------------------------------------------------------------------
// Embedding modulation: one warp per (b, output-row j)
// ---------------------------------------------------------------------------
__global__ void emb_k(const float* __restrict__ t_emb, const float* __restrict__ c_emb,
                      const float* __restrict__ tw, const float* __restrict__ tb,
                      const float* __restrict__ cw, const float* __restrict__ cb) {
    int gw   = (blockIdx.x * blockDim.x + threadIdx.x) >> 5;
    int lane = threadIdx.x & 31;
    int b = gw >> 9;
    int j = gw & 511;
    const float* twr = tw + (size_t)j * C1;
    const float* cwr = cw + (size_t)j * C1;
    const float* te  = t_emb + b * C1;
    const float* ce  = c_emb + b * C1;
    int k0 = lane * 8;
    float4 a0 = *(const float4*)(twr + k0);
    float4 a1 = *(const float4*)(twr + k0 + 4);
    float4 b0 = *(const float4*)(cwr + k0);
    float4 b1 = *(const float4*)(cwr + k0 + 4);
    float4 t0 = *(const float4*)(te + k0);
    float4 t1 = *(const float4*)(te + k0 + 4);
    float4 c0 = *(const float4*)(ce + k0);
    float4 c1 = *(const float4*)(ce + k0 + 4);
    float s = a0.x * t0.x + a0.y * t0.y + a0.z * t0.z + a0.w * t0.w
            + a1.x * t1.x + a1.y * t1.y + a1.z * t1.z + a1.w * t1.w
            + b0.x * c0.x + b0.y * c0.y + b0.z * c0.z + b0.w * c0.w
            + b1.x * c1.x + b1.y * c1.y + b1.z * c1.z + b1.w * c1.w;
#pragma unroll
    for (int off = 16; off >= 1; off >>= 1) s += __shfl_xor_sync(0xffffffffu, s, off);
    if (lane == 0) {
        s += tb[j] + cb[j];
        if (j < C1) g_scale[b * C1 + j] = s;
        else        g_shift[b * C1 + (j - C1)] = s;
    }
}

// ---------------------------------------------------------------------------
// 3-NN + inverse-distance interpolation -> stage0 A plane cols [128,384)
// ---------------------------------------------------------------------------
__global__ void knn_k(const float* __restrict__ xyz1, const float* __restrict__ xyz2) {
    __shared__ float4 ref[SP];
    int b = blockIdx.y;
    int n = blockIdx.x * 128 + threadIdx.x;
    for (int s = threadIdx.x; s < SP; s += 128) {
        float x = xyz2[((size_t)b * 3 + 0) * SP + s];
        float y = xyz2[((size_t)b * 3 + 1) * SP + s];
        float z = xyz2[((size_t)b * 3 + 2) * SP + s];
        ref[s] = make_float4(x, y, z, x * x + y * y + z * z);
    }
    __syncthreads();

    float px = xyz1[((size_t)b * 3 + 0) * NP + n];
    float py = xyz1[((size_t)b * 3 + 1) * NP + n];
    float pz = xyz1[((size_t)b * 3 + 2) * NP + n];
    float n1 = px * px + py * py + pz * pz;

    float d0 = 3.4e38f, d1 = 3.4e38f, d2 = 3.4e38f;
    int   i0 = 0, i1 = 0, i2 = 0;
    for (int s = 0; s < SP; s++) {
        float4 r = ref[s];
        float dot = px * r.x + py * r.y + pz * r.z;
        float d = (-2.0f * dot + n1) + r.w;
        if (d < d2) {
            if (d < d1) {
                d2 = d1; i2 = i1;
                if (d < d0) { d1 = d0; i1 = i0; d0 = d; i0 = s; }
                else        { d1 = d;  i1 = s; }
            } else { d2 = d; i2 = s; }
        }
    }

    float r0 = 1.0f / (d0 + 1e-8f);
    float r1 = 1.0f / (d1 + 1e-8f);
    float r2 = 1.0f / (d2 + 1e-8f);
    float rs = r0 + r1 + r2;
    float w0 = r0 / rs, w1 = r1 / rs, w2 = r2 / rs;

    const float4* p0 = (const float4*)&g_p2t[((size_t)b * SP + i0) * CIN];
    const float4* p1 = (const float4*)&g_p2t[((size_t)b * SP + i1) * CIN];
    const float4* p2 = (const float4*)&g_p2t[((size_t)b * SP + i2) * CIN];
    size_t mof = ((size_t)b * NP + n) * C0 + CSK;
#pragma unroll 4
    for (int c = 0; c < CIN / 4; c++) {
        float4 a = p0[c], bq = p1[c], cq = p2[c];
        __half h[4];
        h[0] = __float2half(a.x * w0 + bq.x * w1 + cq.x * w2);
        h[1] = __float2half(a.y * w0 + bq.y * w1 + cq.y * w2);
        h[2] = __float2half(a.z * w0 + bq.z * w1 + cq.z * w2);
        h[3] = __float2half(a.w * w0 + bq.w * w1 + cq.w * w2);
        *(uint2*)(g_A0 + mof + c * 4) = *(uint2*)h;
    }
}

// ---------------------------------------------------------------------------
// Tensor-core GEMM, single-product fp16, 4-stage cp.async pipeline
// (one __syncthreads per 32-k block; prefetch depth 3).
//   C[m,o] = sum_k A[m,k]*W[o,k] + bias[o]
// BM=BN=128, BK=32, 256 threads (8 warps: 2m x 4n, 64x32 warp tile).
// ---------------------------------------------------------------------------
constexpr int ASTR = 40;                 // smem row stride (fp16)
constexpr int PL   = 128 * ASTR * 2;     // one plane: 10240 B
constexpr int BUFB = 2 * PL;             // A, W: 20480 B
constexpr int NSTG = 4;                  // pipeline stages
constexpr int GSM  = NSTG * BUFB;        // 81920 B dynamic smem

template <int K, int ON, int STAGE>
__global__ __launch_bounds__(256) void gemm_mma(const float* __restrict__ bias) {
    constexpr int NB = K / 32;
    extern __shared__ char smdyn[];

    const __half* Ap = (STAGE == 0) ? g_A0 : (STAGE == 1 ? g_X1 : g_X2);
    const __half* Wp = (STAGE == 0) ? g_W0 : (STAGE == 1 ? g_W1 : g_W2);
    float*        Co = (STAGE == 0) ? g_y1 : (STAGE == 1 ? g_h1 : g_h2);

    const int tid  = threadIdx.x;
    const int m0   = blockIdx.x * 128;
    const int n0   = blockIdx.y * 128;
    const int b    = m0 >> 13;  // NP = 8192
    const int lane = tid & 31;
    const int warp = tid >> 5;
    const int wm   = (warp & 1) * 64;   // warp m-offset
    const int wn   = (warp >> 1) * 32;  // warp n-offset

    const uint32_t sb = sptr(smdyn);

    // cp.async staging: idx = q*256+tid -> row = idx>>2, col8 = (idx&3)*8
    uint32_t soff[2];
    const __half *pA[2], *pW[2];
#pragma unroll
    for (int q = 0; q < 2; q++) {
        int idx = q * 256 + tid;
        int row = idx >> 2, c8 = (idx & 3) * 8;
        soff[q] = (uint32_t)(row * ASTR + c8) * 2;
        pA[q] = Ap + (size_t)(m0 + row) * K + c8;
        pW[q] = Wp + (size_t)(n0 + row) * K + c8;
    }
    auto issue_tile = [&](int kb, int bs) {
        int k0 = kb * 32;
        uint32_t base = sb + bs * BUFB;
#pragma unroll
        for (int q = 0; q < 2; q++) {
            uint32_t d = base + soff[q];
            cp16(d + 0 * PL, pA[q] + k0);
            cp16(d + 1 * PL, pW[q] + k0);
        }
    };

    float c[4][4][4];
#pragma unroll
    for (int i = 0; i < 4; i++)
#pragma unroll
        for (int j = 0; j < 4; j++)
#pragma unroll
            for (int r = 0; r < 4; r++) c[i][j][r] = 0.0f;

    const int lr15 = lane & 15;
    const int lk8  = (lane >> 4) << 3;

    // Prologue: issue up to 3 tiles ahead; always commit to keep numbering.
#pragma unroll
    for (int p = 0; p < NSTG - 1; p++) {
        if (p < NB) issue_tile(p, p);
        cp_commit();
    }

    for (int kb = 0; kb < NB; kb++) {
        int bs = kb & (NSTG - 1);
        cp_wait<NSTG - 2>();   // tile kb has landed (<=2 groups outstanding)
        __syncthreads();       // all warps: tile kb visible AND buffer (kb-1)&3 free

        // Refill the buffer retired last iteration (all warps passed the barrier).
        int nkb = kb + NSTG - 1;
        if (nkb < NB) issue_tile(nkb, nkb & (NSTG - 1));
        cp_commit();

        uint32_t bufbase = sb + bs * BUFB;
        uint32_t aB = bufbase + 0 * PL;
        uint32_t wB = bufbase + 1 * PL;

#pragma unroll
        for (int ks = 0; ks < 32; ks += 16) {
            uint32_t a[4][4], w[4][2];
#pragma unroll
            for (int i = 0; i < 4; i++) {
                uint32_t off = (uint32_t)((wm + i * 16 + lr15) * ASTR + ks + lk8) * 2;
                ldmx4(a[i], aB + off);
            }
#pragma unroll
            for (int p = 0; p < 2; p++) {
                uint32_t off = (uint32_t)((wn + p * 16 + lr15) * ASTR + ks + lk8) * 2;
                uint32_t r[4];
                ldmx4(r, wB + off);
                w[2 * p][0] = r[0]; w[2 * p][1] = r[2];
                w[2 * p + 1][0] = r[1]; w[2 * p + 1][1] = r[3];
            }
#pragma unroll
            for (int i = 0; i < 4; i++)
#pragma unroll
                for (int j = 0; j < 4; j++)
                    mma16816(c[i][j], a[i], w[j]);
        }
    }

    // Epilogue: +bias, store fp32, accumulate GN stats (whole warp -> one group)
    float s = 0.0f, s2 = 0.0f;
#pragma unroll
    for (int i = 0; i < 4; i++) {
#pragma unroll
        for (int j = 0; j < 4; j++) {
            int row = m0 + wm + i * 16 + (lane >> 2);
            int col = n0 + wn + j * 8 + (lane & 3) * 2;
            float b0 = __ldg(bias + col), b1 = __ldg(bias + col + 1);
            float v0 = c[i][j][0] + b0, v1 = c[i][j][1] + b1;
            float v2 = c[i][j][2] + b0, v3 = c[i][j][3] + b1;
            *(float2*)&Co[(size_t)row * ON + col]       = make_float2(v0, v1);
            *(float2*)&Co[(size_t)(row + 8) * ON + col] = make_float2(v2, v3);
            s  += v0 + v1 + v2 + v3;
            s2 += v0 * v0 + v1 * v1 + v2 * v2 + v3 * v3;
        }
    }
#pragma unroll
    for (int off = 16; off >= 1; off >>= 1) {
        s  += __shfl_xor_sync(0xffffffffu, s,  off);
        s2 += __shfl_xor_sync(0xffffffffu, s2, off);
    }
    if (lane == 0) {
        int g = (n0 + wn) / (ON / 8);
        atomicAdd(&g_sum[STAGE * 64 + b * 8 + g], s);
        atomicAdd(&g_sqs[STAGE * 64 + b * 8 + g], s2);
    }
}

// ---------------------------------------------------------------------------
// Finalize GN stats -> per-(b,c) affine coefs: x*a + bb == gn(x)*gw+gb
// ---------------------------------------------------------------------------
template <int STAGE, int CCH>
__global__ void finalize_k(const float* __restrict__ gw, const float* __restrict__ gb) {
    int b = blockIdx.x, c = threadIdx.x;
    int g = c / (CCH / 8);
    float cnt  = (float)(CCH / 8) * (float)NP;
    float mean = g_sum[STAGE * 64 + b * 8 + g] / cnt;
    float var  = g_sqs[STAGE * 64 + b * 8 + g] / cnt - mean * mean;
    float rstd = rsqrtf(var + 1e-5f);
    float a  = rstd * gw[c];
    float bb = gb[c] - mean * a;
    if      (STAGE == 0) { g_cA0[b * CCH + c] = a; g_cB0[b * CCH + c] = bb; }
    else if (STAGE == 1) { g_cA1[b * CCH + c] = a; g_cB1[b * CCH + c] = bb; }
    else                 { g_cA2[b * CCH + c] = a; g_cB2[b * CCH + c] = bb; }
}

// ---------------------------------------------------------------------------
// Final: out[b,c,n] = gn2(h2)*(1+scale)+shift + silu(gn0(y1))  (with transpose)
// ---------------------------------------------------------------------------
__global__ void final_k(float* __restrict__ out) {
    __shared__ float t[32][33];
    int b  = blockIdx.z;
    int n0 = blockIdx.x * 32;
    int c0 = blockIdx.y * 32;
    int tx = threadIdx.x, ty = threadIdx.y;
#pragma unroll
    for (int i = 0; i < 4; i++) {
        int nl = ty + i * 8;
        size_t m = (size_t)b * NP + n0 + nl;
        int c = c0 + tx;
        float h2 = g_h2[m * C1 + c];
        float hn = h2 * g_cA2[b * C1 + c] + g_cB2[b * C1 + c];
        float y1 = g_y1[m * C1 + c];
        float idn = silu_f(y1 * g_cA0[b * C1 + c] + g_cB0[b * C1 + c]);
        float v = hn * (1.0f + g_scale[b * C1 + c]) + g_shift[b * C1 + c] + idn;
        t[nl][tx] = v;
    }
    __syncthreads();
#pragma unroll
    for (int i = 0; i < 4; i++) {
        int cl = ty + i * 8;
        out[((size_t)b * C1 + c0 + cl) * NP + n0 + tx] = t[tx][cl];
    }
}

// ---------------------------------------------------------------------------
// Launch
// ---------------------------------------------------------------------------
extern "C" void kernel_launch(void* const* d_in, const int* in_sizes, int n_in,
                              void* d_out, int out_size) {
    (void)in_sizes; (void)n_in; (void)out_size;
    const float* xyz1    = (const float*)d_in[0];
    const float* points1 = (const float*)d_in[1];
    const float* xyz2    = (const float*)d_in[2];
    const float* points2 = (const float*)d_in[3];
    const float* t_emb   = (const float*)d_in[4];
    const float* c_emb   = (const float*)d_in[5];
    const float* mlp_w   = (const float*)d_in[6];
    const float* mlp_b   = (const float*)d_in[7];
    const float* mlp_gw  = (const float*)d_in[8];
    const float* mlp_gb  = (const float*)d_in[9];
    const float* c1w     = (const float*)d_in[10];
    const float* c1b     = (const float*)d_in[11];
    const float* g1w     = (const float*)d_in[12];
    const float* g1b     = (const float*)d_in[13];
    const float* c2w     = (const float*)d_in[14];
    const float* c2b     = (const float*)d_in[15];
    const float* g2w     = (const float*)d_in[16];
    const float* g2b     = (const float*)d_in[17];
    const float* tw      = (const float*)d_in[18];
    const float* tb      = (const float*)d_in[19];
    const float* cw      = (const float*)d_in[20];
    const float* cb      = (const float*)d_in[21];
    float* out = (float*)d_out;

    cudaFuncSetAttribute((const void*)gemm_mma<C0, C1, 0>,
                         cudaFuncAttributeMaxDynamicSharedMemorySize, GSM);
    cudaFuncSetAttribute((const void*)gemm_mma<C1, CE, 1>,
                         cudaFuncAttributeMaxDynamicSharedMemorySize, GSM);
    cudaFuncSetAttribute((const void*)gemm_mma<CE, C1, 2>,
                         cudaFuncAttributeMaxDynamicSharedMemorySize, GSM);

    zero_k<<<1, 256>>>();
    wsplit_k<0><<<(C1 * C0 / 8 + 255) / 256, 256>>>(mlp_w, C1 * C0 / 8);
    wsplit_k<1><<<(CE * C1 / 8 + 255) / 256, 256>>>(c1w, CE * C1 / 8);
    wsplit_k<2><<<(C1 * CE / 8 + 255) / 256, 256>>>(c2w, C1 * CE / 8);
    tr_p1_k<<<dim3(NP / 32, CSK / 32, BB), dim3(32, 8)>>>(points1);
    tr_p2_k<<<dim3(SP / 32, CIN / 32, BB), dim3(32, 8)>>>(points2);
    emb_k<<<512, 256>>>(t_emb, c_emb, tw, tb, cw, cb);
    knn_k<<<dim3(NP / 128, BB), 128>>>(xyz1, xyz2);

    gemm_mma<C0, C1, 0><<<dim3(MTOT / 128, C1 / 128), 256, GSM>>>(mlp_b);
    finalize_k<0, C1><<<BB, C1>>>(mlp_gw, mlp_gb);
    asplit_k<1><<<MTOT * C1 / 8 / 256, 256>>>();

    gemm_mma<C1, CE, 1><<<dim3(MTOT / 128, CE / 128), 256, GSM>>>(c1b);
    finalize_k<1, CE><<<BB, CE>>>(g1w, g1b);
    asplit_k<2><<<MTOT * CE / 8 / 256, 256>>>();

    gemm_mma<CE, C1, 2><<<dim3(MTOT / 128, C1 / 128), 256, GSM>>>(c2b);
    finalize_k<2, C1><<<BB, C1>>>(g2w, g2b);

    final_k<<<dim3(NP / 32, C1 / 32, BB), dim3(32, 8)>>>(out);
}

// round 15
// speedup vs baseline: 1.0106x; 1.0106x over previous
#include <cuda_runtime.h>
#include <cuda_fp16.h>
#include <cstdint>

// ---------------------------------------------------------------------------
// Problem constants
// ---------------------------------------------------------------------------
constexpr int BB   = 8;
constexpr int NP   = 8192;
constexpr int SP   = 2048;
constexpr int CIN  = 256;
constexpr int CSK  = 128;
constexpr int C0   = 384;     // IN+SKIP
constexpr int C1   = 256;     // OUT
constexpr int CE   = 1024;    // OUT*EXP
constexpr int MTOT = BB * NP; // 65536 rows

// ---------------------------------------------------------------------------
// Scratch (device globals; no dynamic allocation allowed)
// ---------------------------------------------------------------------------
static __device__ __half g_A0[MTOT * C0];   // stage0 A plane (fp16)
static __device__ __half g_X1[MTOT * C1];   // stage1 A plane
static __device__ __half g_X2[MTOT * CE];   // stage2 A plane
static __device__ __half g_W0[C1 * C0];
static __device__ __half g_W1[CE * C1];
static __device__ __half g_W2[C1 * CE];
static __device__ float g_p2t[BB * SP * CIN];  // points2 transposed [b, s, c]
static __device__ float g_y1 [MTOT * C1];      // conv0 out (pre-GN)
static __device__ float g_h1 [MTOT * CE];      // conv1 out (pre-GN)
static __device__ float g_h2 [MTOT * C1];      // conv2 out (pre-GN)
static __device__ float g_sum[3 * 64];
static __device__ float g_sqs[3 * 64];
static __device__ float g_cA0[BB * C1], g_cB0[BB * C1];
static __device__ float g_cA1[BB * CE], g_cB1[BB * CE];
static __device__ float g_cA2[BB * C1], g_cB2[BB * C1];
static __device__ float g_scale[BB * C1], g_shift[BB * C1];

__device__ __forceinline__ float silu_f(float x) {
    return __fdividef(x, 1.0f + __expf(-x));
}

// ---------------------------------------------------------------------------
// MMA / cp.async helpers (legacy fp16 tensor-core path; plain sm_100 target)
// ---------------------------------------------------------------------------
__device__ __forceinline__ uint32_t sptr(const void* p) {
    return (uint32_t)__cvta_generic_to_shared(p);
}
__device__ __forceinline__ void ldmx4(uint32_t* r, uint32_t addr) {
    asm volatile("ldmatrix.sync.aligned.m8n8.x4.shared.b16 {%0,%1,%2,%3}, [%4];\n"
                 : "=r"(r[0]), "=r"(r[1]), "=r"(r[2]), "=r"(r[3]) : "r"(addr));
}
__device__ __forceinline__ void mma16816(float* c, const uint32_t* a, const uint32_t* b) {
    asm volatile(
        "mma.sync.aligned.m16n8k16.row.col.f32.f16.f16.f32 "
        "{%0,%1,%2,%3}, {%4,%5,%6,%7}, {%8,%9}, {%0,%1,%2,%3};\n"
        : "+f"(c[0]), "+f"(c[1]), "+f"(c[2]), "+f"(c[3])
        : "r"(a[0]), "r"(a[1]), "r"(a[2]), "r"(a[3]), "r"(b[0]), "r"(b[1]));
}
__device__ __forceinline__ void cp16(uint32_t dst, const void* src) {
    asm volatile("cp.async.cg.shared.global [%0], [%1], 16;\n" :: "r"(dst), "l"(src));
}
__device__ __forceinline__ void cp_commit() {
    asm volatile("cp.async.commit_group;\n" ::: "memory");
}
template <int N>
__device__ __forceinline__ void cp_wait() {
    asm volatile("cp.async.wait_group %0;\n" :: "n"(N) : "memory");
}

// ---------------------------------------------------------------------------
// Zero the stats accumulators
// ---------------------------------------------------------------------------
__global__ void zero_k() {
    int i = threadIdx.x;
    if (i < 192) { g_sum[i] = 0.0f; g_sqs[i] = 0.0f; }
}

// ---------------------------------------------------------------------------
// Weight convert: fp32 -> fp16 plane (8 elems/thread)
// ---------------------------------------------------------------------------
template <int WS>
__global__ void wsplit_k(const float* __restrict__ w, int n8) {
    int i = blockIdx.x * 256 + threadIdx.x;
    if (i >= n8) return;
    __half* hi = (WS == 0) ? g_W0 : (WS == 1 ? g_W1 : g_W2);
    const float4* wp = (const float4*)w + 2 * i;
    float4 a = wp[0], b = wp[1];
    __half h[8];
    h[0] = __float2half(a.x); h[1] = __float2half(a.y);
    h[2] = __float2half(a.z); h[3] = __float2half(a.w);
    h[4] = __float2half(b.x); h[5] = __float2half(b.y);
    h[6] = __float2half(b.z); h[7] = __float2half(b.w);
    *(uint4*)(hi + (size_t)i * 8) = *(uint4*)h;
}

// ---------------------------------------------------------------------------
// Activation convert: x -> silu(x*cA + cB) -> fp16 plane (8 elems/thread)
// ---------------------------------------------------------------------------
template <int STAGE>
__global__ void asplit_k() {
    constexpr int C = (STAGE == 1) ? C1 : CE;
    const float* X  = (STAGE == 1) ? g_y1  : g_h1;
    const float* cA = (STAGE == 1) ? g_cA0 : g_cA1;
    const float* cB = (STAGE == 1) ? g_cB0 : g_cB1;
    __half* oh = (STAGE == 1) ? g_X1 : g_X2;

    size_t i = (size_t)blockIdx.x * 256 + threadIdx.x;   // per 8 elements
    int m  = (int)(i / (C / 8));
    int c0 = (int)(i % (C / 8)) * 8;
    int b  = m >> 13;
    const float4* xp = (const float4*)(X + (size_t)m * C + c0);
    float4 x0 = xp[0], x1 = xp[1];
    const float* a = cA + b * C + c0;
    const float* s = cB + b * C + c0;
    __half h[8];
    h[0] = __float2half(silu_f(x0.x * a[0] + s[0]));
    h[1] = __float2half(silu_f(x0.y * a[1] + s[1]));
    h[2] = __float2half(silu_f(x0.z * a[2] + s[2]));
    h[3] = __float2half(silu_f(x0.w * a[3] + s[3]));
    h[4] = __float2half(silu_f(x1.x * a[4] + s[4]));
    h[5] = __float2half(silu_f(x1.y * a[5] + s[5]));
    h[6] = __float2half(silu_f(x1.z * a[6] + s[6]));
    h[7] = __float2half(silu_f(x1.w * a[7] + s[7]));
    *(uint4*)(oh + (size_t)m * C + c0) = *(uint4*)h;
}

// ---------------------------------------------------------------------------
// Transpose points1 [B,128,N] -> stage0 A plane, columns [0,128)
// ---------------------------------------------------------------------------
__global__ void tr_p1_k(const float* __restrict__ src) {
    __shared__ float t[32][33];
    int b  = blockIdx.z;
    int n0 = blockIdx.x * 32;
    int c0 = blockIdx.y * 32;
    int tx = threadIdx.x, ty = threadIdx.y;
#pragma unroll
    for (int i = 0; i < 4; i++) {
        int cl = ty + i * 8;
        t[cl][tx] = src[((size_t)b * CSK + (c0 + cl)) * NP + n0 + tx];
    }
    __syncthreads();
#pragma unroll
    for (int i = 0; i < 4; i++) {
        int nl = ty + i * 8;
        size_t m = (size_t)b * NP + n0 + nl;
        g_A0[m * C0 + c0 + tx] = __float2half(t[tx][nl]);
    }
}

// ---------------------------------------------------------------------------
// Transpose points2 [B,256,S] -> g_p2t [b, s, c]
// ---------------------------------------------------------------------------
__global__ void tr_p2_k(const float* __restrict__ src) {
    __shared__ float t[32][33];
    int b  = blockIdx.z;
    int s0 = blockIdx.x * 32;
    int c0 = blockIdx.y * 32;
    int tx = threadIdx.x, ty = threadIdx.y;
#pragma unroll
    for (int i = 0; i < 4; i++) {
        int cl = ty + i * 8;
        t[cl][tx] = src[((size_t)b * CIN + (c0 + cl)) * SP + s0 + tx];
    }
    __syncthreads();
#pragma unroll
    for (int i = 0; i < 4; i++) {
        int sl = ty + i * 8;
        g_p2t[((size_t)b * SP + (s0 + sl)) * CIN + c0 + tx] = t[tx][sl];
    }
}

// ---------------------------------------------------------------------------
// Embedding modulation: one warp per (b, output-row j)
// ---------------------------------------------------------------------------
__global__ void emb_k(const float* __restrict__ t_emb, const float* __restrict__ c_emb,
                      const float* __restrict__ tw, const float* __restrict__ tb,
                      const float* __restrict__ cw, const float* __restrict__ cb) {
    int gw   = (blockIdx.x * blockDim.x + threadIdx.x) >> 5;
    int lane = threadIdx.x & 31;
    int b = gw >> 9;
    int j = gw & 511;
    const float* twr = tw + (size_t)j * C1;
    const float* cwr = cw + (size_t)j * C1;
    const float* te  = t_emb + b * C1;
    const float* ce  = c_emb + b * C1;
    int k0 = lane * 8;
    float4 a0 = *(const float4*)(twr + k0);
    float4 a1 = *(const float4*)(twr + k0 + 4);
    float4 b0 = *(const float4*)(cwr + k0);
    float4 b1 = *(const float4*)(cwr + k0 + 4);
    float4 t0 = *(const float4*)(te + k0);
    float4 t1 = *(const float4*)(te + k0 + 4);
    float4 c0 = *(const float4*)(ce + k0);
    float4 c1 = *(const float4*)(ce + k0 + 4);
    float s = a0.x * t0.x + a0.y * t0.y + a0.z * t0.z + a0.w * t0.w
            + a1.x * t1.x + a1.y * t1.y + a1.z * t1.z + a1.w * t1.w
            + b0.x * c0.x + b0.y * c0.y + b0.z * c0.z + b0.w * c0.w
            + b1.x * c1.x + b1.y * c1.y + b1.z * c1.z + b1.w * c1.w;
#pragma unroll
    for (int off = 16; off >= 1; off >>= 1) s += __shfl_xor_sync(0xffffffffu, s, off);
    if (lane == 0) {
        s += tb[j] + cb[j];
        if (j < C1) g_scale[b * C1 + j] = s;
        else        g_shift[b * C1 + (j - C1)] = s;
    }
}

// ---------------------------------------------------------------------------
// 3-NN + inverse-distance interpolation -> stage0 A plane cols [128,384)
// ---------------------------------------------------------------------------
__global__ void knn_k(const float* __restrict__ xyz1, const float* __restrict__ xyz2) {
    __shared__ float4 ref[SP];
    int b = blockIdx.y;
    int n = blockIdx.x * 128 + threadIdx.x;
    for (int s = threadIdx.x; s < SP; s += 128) {
        float x = xyz2[((size_t)b * 3 + 0) * SP + s];
        float y = xyz2[((size_t)b * 3 + 1) * SP + s];
        float z = xyz2[((size_t)b * 3 + 2) * SP + s];
        ref[s] = make_float4(x, y, z, x * x + y * y + z * z);
    }
    __syncthreads();

    float px = xyz1[((size_t)b * 3 + 0) * NP + n];
    float py = xyz1[((size_t)b * 3 + 1) * NP + n];
    float pz = xyz1[((size_t)b * 3 + 2) * NP + n];
    float n1 = px * px + py * py + pz * pz;

    float d0 = 3.4e38f, d1 = 3.4e38f, d2 = 3.4e38f;
    int   i0 = 0, i1 = 0, i2 = 0;
    for (int s = 0; s < SP; s++) {
        float4 r = ref[s];
        float dot = px * r.x + py * r.y + pz * r.z;
        float d = (-2.0f * dot + n1) + r.w;
        if (d < d2) {
            if (d < d1) {
                d2 = d1; i2 = i1;
                if (d < d0) { d1 = d0; i1 = i0; d0 = d; i0 = s; }
                else        { d1 = d;  i1 = s; }
            } else { d2 = d; i2 = s; }
        }
    }

    float r0 = 1.0f / (d0 + 1e-8f);
    float r1 = 1.0f / (d1 + 1e-8f);
    float r2 = 1.0f / (d2 + 1e-8f);
    float rs = r0 + r1 + r2;
    float w0 = r0 / rs, w1 = r1 / rs, w2 = r2 / rs;

    const float4* p0 = (const float4*)&g_p2t[((size_t)b * SP + i0) * CIN];
    const float4* p1 = (const float4*)&g_p2t[((size_t)b * SP + i1) * CIN];
    const float4* p2 = (const float4*)&g_p2t[((size_t)b * SP + i2) * CIN];
    size_t mof = ((size_t)b * NP + n) * C0 + CSK;
#pragma unroll 4
    for (int c = 0; c < CIN / 4; c++) {
        float4 a = p0[c], bq = p1[c], cq = p2[c];
        __half h[4];
        h[0] = __float2half(a.x * w0 + bq.x * w1 + cq.x * w2);
        h[1] = __float2half(a.y * w0 + bq.y * w1 + cq.y * w2);
        h[2] = __float2half(a.z * w0 + bq.z * w1 + cq.z * w2);
        h[3] = __float2half(a.w * w0 + bq.w * w1 + cq.w * w2);
        *(uint2*)(g_A0 + mof + c * 4) = *(uint2*)h;
    }
}

// ---------------------------------------------------------------------------
// Tensor-core GEMM, single-product fp16, 4-stage cp.async pipeline.
// CTA tile 128x128, 4 warps (2x2), warp tile 64x64 -> 65.5 FLOP per smem byte
// (1.5x R13) and 2 warps/SMSP (half the LDSM crossbar pressure).
//   C[m,o] = sum_k A[m,k]*W[o,k] + bias[o]
// ---------------------------------------------------------------------------
constexpr int ASTR = 40;                 // smem row stride (fp16)
constexpr int PL   = 128 * ASTR * 2;     // one plane: 10240 B
constexpr int BUFB = 2 * PL;             // A, W: 20480 B
constexpr int NSTG = 4;                  // pipeline stages
constexpr int GSM  = NSTG * BUFB;        // 81920 B dynamic smem

template <int K, int ON, int STAGE>
__global__ __launch_bounds__(128) void gemm_mma(const float* __restrict__ bias) {
    constexpr int NB = K / 32;
    extern __shared__ char smdyn[];

    const __half* Ap = (STAGE == 0) ? g_A0 : (STAGE == 1 ? g_X1 : g_X2);
    const __half* Wp = (STAGE == 0) ? g_W0 : (STAGE == 1 ? g_W1 : g_W2);
    float*        Co = (STAGE == 0) ? g_y1 : (STAGE == 1 ? g_h1 : g_h2);

    const int tid  = threadIdx.x;
    const int m0   = blockIdx.x * 128;
    const int n0   = blockIdx.y * 128;
    const int b    = m0 >> 13;  // NP = 8192
    const int lane = tid & 31;
    const int warp = tid >> 5;
    const int wm   = (warp & 1) * 64;    // warp m-offset
    const int wn   = (warp >> 1) * 64;   // warp n-offset

    const uint32_t sb = sptr(smdyn);

    // cp.async staging (128 thr): idx = q*128+tid -> row = idx>>2, col8=(idx&3)*8
    uint32_t soff[4];
    const __half *pA[4], *pW[4];
#pragma unroll
    for (int q = 0; q < 4; q++) {
        int idx = q * 128 + tid;
        int row = idx >> 2, c8 = (idx & 3) * 8;
        soff[q] = (uint32_t)(row * ASTR + c8) * 2;
        pA[q] = Ap + (size_t)(m0 + row) * K + c8;
        pW[q] = Wp + (size_t)(n0 + row) * K + c8;
    }
    auto issue_tile = [&](int kb, int bs) {
        int k0 = kb * 32;
        uint32_t base = sb + bs * BUFB;
#pragma unroll
        for (int q = 0; q < 4; q++) {
            uint32_t d = base + soff[q];
            cp16(d + 0 * PL, pA[q] + k0);
            cp16(d + 1 * PL, pW[q] + k0);
        }
    };

    float c[4][8][4];
#pragma unroll
    for (int i = 0; i < 4; i++)
#pragma unroll
        for (int j = 0; j < 8; j++)
#pragma unroll
            for (int r = 0; r < 4; r++) c[i][j][r] = 0.0f;

    const int lr15 = lane & 15;
    const int lk8  = (lane >> 4) << 3;

    // Prologue: issue up to 3 tiles ahead; always commit to keep numbering.
#pragma unroll
    for (int p = 0; p < NSTG - 1; p++) {
        if (p < NB) issue_tile(p, p);
        cp_commit();
    }

    for (int kb = 0; kb < NB; kb++) {
        int bs = kb & (NSTG - 1);
        cp_wait<NSTG - 2>();   // tile kb has landed (<=2 groups outstanding)
        __syncthreads();       // tile kb visible AND buffer (kb-1)&3 free

        int nkb = kb + NSTG - 1;
        if (nkb < NB) issue_tile(nkb, nkb & (NSTG - 1));
        cp_commit();

        uint32_t bufbase = sb + bs * BUFB;
        uint32_t aB = bufbase + 0 * PL;
        uint32_t wB = bufbase + 1 * PL;

#pragma unroll
        for (int ks = 0; ks < 32; ks += 16) {
            uint32_t a[4][4], w[8][2];
#pragma unroll
            for (int i = 0; i < 4; i++) {
                uint32_t off = (uint32_t)((wm + i * 16 + lr15) * ASTR + ks + lk8) * 2;
                ldmx4(a[i], aB + off);
            }
#pragma unroll
            for (int p = 0; p < 4; p++) {
                uint32_t off = (uint32_t)((wn + p * 16 + lr15) * ASTR + ks + lk8) * 2;
                uint32_t r[4];
                ldmx4(r, wB + off);
                w[2 * p][0] = r[0]; w[2 * p][1] = r[2];
                w[2 * p + 1][0] = r[1]; w[2 * p + 1][1] = r[3];
            }
#pragma unroll
            for (int i = 0; i < 4; i++)
#pragma unroll
                for (int j = 0; j < 8; j++)
                    mma16816(c[i][j], a[i], w[j]);
        }
    }

    // Epilogue: +bias, store fp32, GN stats. A warp spans two 32-col groups
    // (halves j<4 and j>=4) when ON=256; accumulate per half.
    float s[2] = {0.0f, 0.0f}, s2[2] = {0.0f, 0.0f};
#pragma unroll
    for (int i = 0; i < 4; i++) {
#pragma unroll
        for (int j = 0; j < 8; j++) {
            int half = j >> 2;
            int row = m0 + wm + i * 16 + (lane >> 2);
            int col = n0 + wn + j * 8 + (lane & 3) * 2;
            float b0 = __ldg(bias + col), b1 = __ldg(bias + col + 1);
            float v0 = c[i][j][0] + b0, v1 = c[i][j][1] + b1;
            float v2 = c[i][j][2] + b0, v3 = c[i][j][3] + b1;
            *(float2*)&Co[(size_t)row * ON + col]       = make_float2(v0, v1);
            *(float2*)&Co[(size_t)(row + 8) * ON + col] = make_float2(v2, v3);
            s[half]  += v0 + v1 + v2 + v3;
            s2[half] += v0 * v0 + v1 * v1 + v2 * v2 + v3 * v3;
        }
    }
#pragma unroll
    for (int h = 0; h < 2; h++) {
#pragma unroll
        for (int off = 16; off >= 1; off >>= 1) {
            s[h]  += __shfl_xor_sync(0xffffffffu, s[h],  off);
            s2[h] += __shfl_xor_sync(0xffffffffu, s2[h], off);
        }
        if (lane == 0) {
            int g = (n0 + wn + h * 32) / (ON / 8);
            atomicAdd(&g_sum[STAGE * 64 + b * 8 + g], s[h]);
            atomicAdd(&g_sqs[STAGE * 64 + b * 8 + g], s2[h]);
        }
    }
}

// ---------------------------------------------------------------------------
// Finalize GN stats -> per-(b,c) affine coefs: x*a + bb == gn(x)*gw+gb
// ---------------------------------------------------------------------------
template <int STAGE, int CCH>
__global__ void finalize_k(const float* __restrict__ gw, const float* __restrict__ gb) {
    int b = blockIdx.x, c = threadIdx.x;
    int g = c / (CCH / 8);
    float cnt  = (float)(CCH / 8) * (float)NP;
    float mean = g_sum[STAGE * 64 + b * 8 + g] / cnt;
    float var  = g_sqs[STAGE * 64 + b * 8 + g] / cnt - mean * mean;
    float rstd = rsqrtf(var + 1e-5f);
    float a  = rstd * gw[c];
    float bb = gb[c] - mean * a;
    if      (STAGE == 0) { g_cA0[b * CCH + c] = a; g_cB0[b * CCH + c] = bb; }
    else if (STAGE == 1) { g_cA1[b * CCH + c] = a; g_cB1[b * CCH + c] = bb; }
    else                 { g_cA2[b * CCH + c] = a; g_cB2[b * CCH + c] = bb; }
}

// ---------------------------------------------------------------------------
// Final: out[b,c,n] = gn2(h2)*(1+scale)+shift + silu(gn0(y1))  (with transpose)
// ---------------------------------------------------------------------------
__global__ void final_k(float* __restrict__ out) {
    __shared__ float t[32][33];
    int b  = blockIdx.z;
    int n0 = blockIdx.x * 32;
    int c0 = blockIdx.y * 32;
    int tx = threadIdx.x, ty = threadIdx.y;
#pragma unroll
    for (int i = 0; i < 4; i++) {
        int nl = ty + i * 8;
        size_t m = (size_t)b * NP + n0 + nl;
        int c = c0 + tx;
        float h2 = g_h2[m * C1 + c];
        float hn = h2 * g_cA2[b * C1 + c] + g_cB2[b * C1 + c];
        float y1 = g_y1[m * C1 + c];
        float idn = silu_f(y1 * g_cA0[b * C1 + c] + g_cB0[b * C1 + c]);
        float v = hn * (1.0f + g_scale[b * C1 + c]) + g_shift[b * C1 + c] + idn;
        t[nl][tx] = v;
    }
    __syncthreads();
#pragma unroll
    for (int i = 0; i < 4; i++) {
        int cl = ty + i * 8;
        out[((size_t)b * C1 + c0 + cl) * NP + n0 + tx] = t[tx][cl];
    }
}

// ---------------------------------------------------------------------------
// Launch
// ---------------------------------------------------------------------------
extern "C" void kernel_launch(void* const* d_in, const int* in_sizes, int n_in,
                              void* d_out, int out_size) {
    (void)in_sizes; (void)n_in; (void)out_size;
    const float* xyz1    = (const float*)d_in[0];
    const float* points1 = (const float*)d_in[1];
    const float* xyz2    = (const float*)d_in[2];
    const float* points2 = (const float*)d_in[3];
    const float* t_emb   = (const float*)d_in[4];
    const float* c_emb   = (const float*)d_in[5];
    const float* mlp_w   = (const float*)d_in[6];
    const float* mlp_b   = (const float*)d_in[7];
    const float* mlp_gw  = (const float*)d_in[8];
    const float* mlp_gb  = (const float*)d_in[9];
    const float* c1w     = (const float*)d_in[10];
    const float* c1b     = (const float*)d_in[11];
    const float* g1w     = (const float*)d_in[12];
    const float* g1b     = (const float*)d_in[13];
    const float* c2w     = (const float*)d_in[14];
    const float* c2b     = (const float*)d_in[15];
    const float* g2w     = (const float*)d_in[16];
    const float* g2b     = (const float*)d_in[17];
    const float* tw      = (const float*)d_in[18];
    const float* tb      = (const float*)d_in[19];
    const float* cw      = (const float*)d_in[20];
    const float* cb      = (const float*)d_in[21];
    float* out = (float*)d_out;

    cudaFuncSetAttribute((const void*)gemm_mma<C0, C1, 0>,
                         cudaFuncAttributeMaxDynamicSharedMemorySize, GSM);
    cudaFuncSetAttribute((const void*)gemm_mma<C1, CE, 1>,
                         cudaFuncAttributeMaxDynamicSharedMemorySize, GSM);
    cudaFuncSetAttribute((const void*)gemm_mma<CE, C1, 2>,
                         cudaFuncAttributeMaxDynamicSharedMemorySize, GSM);

    zero_k<<<1, 256>>>();
    wsplit_k<0><<<(C1 * C0 / 8 + 255) / 256, 256>>>(mlp_w, C1 * C0 / 8);
    wsplit_k<1><<<(CE * C1 / 8 + 255) / 256, 256>>>(c1w, CE * C1 / 8);
    wsplit_k<2><<<(C1 * CE / 8 + 255) / 256, 256>>>(c2w, C1 * CE / 8);
    tr_p1_k<<<dim3(NP / 32, CSK / 32, BB), dim3(32, 8)>>>(points1);
    tr_p2_k<<<dim3(SP / 32, CIN / 32, BB), dim3(32, 8)>>>(points2);
    emb_k<<<512, 256>>>(t_emb, c_emb, tw, tb, cw, cb);
    knn_k<<<dim3(NP / 128, BB), 128>>>(xyz1, xyz2);

    gemm_mma<C0, C1, 0><<<dim3(MTOT / 128, C1 / 128), 128, GSM>>>(mlp_b);
    finalize_k<0, C1><<<BB, C1>>>(mlp_gw, mlp_gb);
    asplit_k<1><<<MTOT * C1 / 8 / 256, 256>>>();

    gemm_mma<C1, CE, 1><<<dim3(MTOT / 128, CE / 128), 128, GSM>>>(c1b);
    finalize_k<1, CE><<<BB, CE>>>(g1w, g1b);
    asplit_k<2><<<MTOT * CE / 8 / 256, 256>>>();

    gemm_mma<CE, C1, 2><<<dim3(MTOT / 128, C1 / 128), 128, GSM>>>(c2b);
    finalize_k<2, C1><<<BB, C1>>>(g2w, g2b);

    final_k<<<dim3(NP / 32, C1 / 32, BB), dim3(32, 8)>>>(out);
}